// round 14
// baseline (speedup 1.0000x reference)
#include <cuda_runtime.h>
#include <cuda_bf16.h>
#include <cstdint>

typedef unsigned long long u64;
typedef unsigned int u32;
typedef unsigned short u16;

#define B_ROWS 2048
#define N_TRAIN 100000
#define KDIM 1024
#define NCLS 1000
#define MAXK 200
#define NSAMP 2048         // sampled train rows for loose threshold
#define SRANK 24           // sampled rank -> true rank ~1170
#define CCAP2 3584         // loose-candidate cap per row (~7 sigma)
#define NSURV 1024         // survivor cap per row after refine
#define TINV (1.0f / 0.07f)
#define RESC_WIN 3.5f      // exact-rescore window below max (1.5 cut + 2*eps)

// device scratch (allocation-free)
__device__ __nv_bfloat16 g_fb[(size_t)B_ROWS * KDIM];     // 4 MB
__device__ __nv_bfloat16 g_tb[(size_t)N_TRAIN * KDIM];    // 205 MB
__device__ u16 g_samp[(size_t)B_ROWS * NSAMP];            // 8 MB (keys)
__device__ u32 g_thr[B_ROWS];                             // loose per-row key
__device__ u64 g_cand2[(size_t)B_ROWS * CCAP2];           // 59 MB (key|idx)
__device__ u32 g_cnt2[B_ROWS];

// ---------------------------------------------------------------- helpers
__device__ __forceinline__ u32 smem_u32(const void* p) {
    u32 a;
    asm("{ .reg .u64 t; cvta.to.shared.u64 t, %1; cvt.u32.u64 %0, t; }"
        : "=r"(a) : "l"(p));
    return a;
}
#define SWZ(x) ((x) ^ (((x) >> 3) & 0x70))

// 16-bit order keys over bf16 bit patterns
__device__ __forceinline__ u32 enc16(u32 x) {
    return (x & 0x8000u) ? ((~x) & 0xFFFFu) : (x | 0x8000u);
}
__device__ __forceinline__ float dec16(u32 k) {
    u32 b = (k & 0x8000u) ? (k & 0x7FFFu) : ((~k) & 0xFFFFu);
    return __uint_as_float(b << 16);
}
__device__ __forceinline__ u32 enc32(float f) {
    u32 u = __float_as_uint(f);
    return (u & 0x80000000u) ? ~u : (u | 0x80000000u);
}
__device__ __forceinline__ float dec32(u32 u) {
    return (u & 0x80000000u) ? __uint_as_float(u & 0x7FFFFFFFu)
                             : __uint_as_float(~u);
}

__device__ __forceinline__ void cp16(u32 dst, const void* src) {
    asm volatile("cp.async.cg.shared.global [%0], [%1], 16;"
                 :: "r"(dst), "l"(src) : "memory");
}
__device__ __forceinline__ void ldmx4(u32* r, u32 addr) {
    asm volatile("ldmatrix.sync.aligned.m8n8.x4.shared.b16 {%0,%1,%2,%3},[%4];"
                 : "=r"(r[0]), "=r"(r[1]), "=r"(r[2]), "=r"(r[3]) : "r"(addr));
}
__device__ __forceinline__ void mma16816(float* d, const u32* a, const u32* b) {
    asm volatile(
        "mma.sync.aligned.m16n8k16.row.col.f32.bf16.bf16.f32 "
        "{%0,%1,%2,%3},{%4,%5,%6,%7},{%8,%9},{%0,%1,%2,%3};"
        : "+f"(d[0]), "+f"(d[1]), "+f"(d[2]), "+f"(d[3])
        : "r"(a[0]), "r"(a[1]), "r"(a[2]), "r"(a[3]), "r"(b[0]), "r"(b[1]));
}
// mbarrier ops (sm_80/90-era PTX, legal on base compute_103)
__device__ __forceinline__ void mbar_init(u32 mbar, u32 cnt) {
    asm volatile("mbarrier.init.shared.b64 [%0], %1;" :: "r"(mbar), "r"(cnt)
                 : "memory");
}
__device__ __forceinline__ void mbar_arrive(u32 mbar) {
    asm volatile("mbarrier.arrive.shared.b64 _, [%0];" :: "r"(mbar) : "memory");
}
// .noinc is REQUIRED (non-noinc increments expected count -> deadlock, R10).
__device__ __forceinline__ void cpasync_arrive(u32 mbar) {
    asm volatile("cp.async.mbarrier.arrive.noinc.shared.b64 [%0];" :: "r"(mbar)
                 : "memory");
}
__device__ __forceinline__ void waitp(u32 mbar, u32 parity) {
    asm volatile(
        "{\n\t.reg .pred P;\n\t"
        "WL%=:\n\t"
        "mbarrier.try_wait.parity.acquire.cta.shared::cta.b64 P, [%0], %1, 0x989680;\n\t"
        "@P bra.uni WD%=;\n\t"
        "bra.uni WL%=;\n\t"
        "WD%=:\n\t}"
        :: "r"(mbar), "r"(parity) : "memory");
}

// ---------------------------------------------------------- fp32 -> bf16
__global__ __launch_bounds__(256) void conv_kernel(const float* __restrict__ src,
                                                   __nv_bfloat16* dst, int n4) {
    for (int i = blockIdx.x * 256 + threadIdx.x; i < n4; i += gridDim.x * 256) {
        float4 v = ((const float4*)src)[i];
        u32 lo, hi;
        asm("cvt.rn.bf16x2.f32 %0, %1, %2;" : "=r"(lo) : "f"(v.y), "f"(v.x));
        asm("cvt.rn.bf16x2.f32 %0, %1, %2;" : "=r"(hi) : "f"(v.w), "f"(v.z));
        ((uint2*)dst)[i] = make_uint2(lo, hi);
    }
}

__global__ void zero_cnt() { g_cnt2[blockIdx.x * 256 + threadIdx.x] = 0; }

// ------------------------------------------------- shared GEMM machinery
// CTA tile 128x128, BK=64, 8 warps (2x4), warp tile 64x32, 3-stage cp.async.
#define GM 128
#define GN 128
#define GK 64
#define STAGE_B (GM * GK * 2 + GN * GK * 2)   // 32768
#define NSTAGE 3
#define NK (KDIM / GK)                        // 16
#define GEMM_SMEM (NSTAGE * STAGE_B + 64)     // stages + 6 mbarriers

__device__ __forceinline__ void issue_tile(u32 sbase, int tid, int m_base,
                                           int n_base, int kt) {
#pragma unroll
    for (int q = 0; q < 4; q++) {
        int idx = tid + q * 256;
        int r = idx >> 3, c = idx & 7;
        const void* src = g_fb + ((size_t)(m_base + r) << 10) + kt + c * 8;
        cp16(sbase + SWZ(r * 128 + c * 16), src);
    }
    u32 bbase = sbase + GM * GK * 2;
#pragma unroll
    for (int q = 0; q < 4; q++) {
        int idx = tid + q * 256;
        int r = idx >> 3, c = idx & 7;
        int n = n_base + r;
        if (n >= N_TRAIN) n = N_TRAIN - 1;   // clamp: finite garbage, never emitted
        const void* src = g_tb + ((size_t)n << 10) + kt + c * 8;
        cp16(bbase + SWZ(r * 128 + c * 16), src);
    }
    asm volatile("cp.async.commit_group;" ::: "memory");
}

// MMA body for one resident stage (reads abase/bbase, updates acc)
#define STAGE_MMAS(abase_, bbase_)                                              \
    _Pragma("unroll")                                                           \
    for (int ks = 0; ks < 4; ks++) {                                            \
        u32 afrag[4][4], bfrag[2][4];                                           \
        _Pragma("unroll")                                                       \
        for (int mi = 0; mi < 4; mi++) {                                        \
            int row = wm0 + mi * 16 + a_row_sel;                                \
            int col = ks * 16 + a_kh * 8;                                       \
            ldmx4(afrag[mi], (abase_) + SWZ(row * 128 + col * 2));              \
        }                                                                       \
        _Pragma("unroll")                                                       \
        for (int p = 0; p < 2; p++) {                                           \
            int row = wn0 + p * 16 + b_n_sel;                                   \
            int col = ks * 16 + b_kh * 8;                                       \
            ldmx4(bfrag[p], (bbase_) + SWZ(row * 128 + col * 2));               \
        }                                                                       \
        _Pragma("unroll")                                                       \
        for (int mi = 0; mi < 4; mi++)                                          \
            _Pragma("unroll")                                                   \
            for (int nj = 0; nj < 4; nj++)                                      \
                mma16816(acc[mi][nj], afrag[mi],                                \
                         &bfrag[nj >> 1][(nj & 1) * 2]);                        \
    }

// barrier-lockstep mainloop (used by gemm_mini; proven config)
#define GEMM_MAINLOOP(acc)                                                      \
    issue_tile(sb, tid, m_base, n_base, 0);                                     \
    issue_tile(sb + STAGE_B, tid, m_base, n_base, GK);                          \
    const int a_row_sel = lane & 15;                                            \
    const int a_kh = (lane >> 4) & 1;                                           \
    const int b_n_sel = (lane & 7) + ((lane & 16) >> 1);                        \
    const int b_kh = (lane >> 3) & 1;                                           \
    for (int kt = 0; kt < NK; kt++) {                                           \
        asm volatile("cp.async.wait_group 1;" ::: "memory");                    \
        __syncthreads();                                                        \
        if (kt + 2 < NK)                                                        \
            issue_tile(sb + ((kt + 2) % NSTAGE) * STAGE_B, tid, m_base,         \
                       n_base, (kt + 2) * GK);                                  \
        const u32 abase = sb + (kt % NSTAGE) * STAGE_B;                         \
        const u32 bbase = abase + GM * GK * 2;                                  \
        STAGE_MMAS(abase, bbase)                                                \
    }                                                                           \
    asm volatile("cp.async.wait_group 0;" ::: "memory");                        \
    __syncthreads();

// --- mini GEMM: sampled columns (first NSAMP train rows) -> g_samp keys
__global__ __launch_bounds__(256) void gemm_mini() {
    extern __shared__ char dsm[];
    const u32 sb = smem_u32(dsm);
    const int tid = threadIdx.x;
    const int wid = tid >> 5, lane = tid & 31;
    const int m_base = blockIdx.x * GM;
    const int n_base = blockIdx.y * GN;
    const int warp_m = wid >> 2, warp_n = wid & 3;
    const int wm0 = warp_m * 64, wn0 = warp_n * 32;

    float acc[4][4][4];
#pragma unroll
    for (int i = 0; i < 4; i++)
#pragma unroll
        for (int j = 0; j < 4; j++)
#pragma unroll
            for (int q = 0; q < 4; q++) acc[i][j][q] = 0.0f;

    GEMM_MAINLOOP(acc)

    // epilogue: keys -> smem [128][68 u32] -> coalesced store to g_samp
    u32* ep = (u32*)dsm;
    const int tg = lane >> 2, tc = lane & 3;
#pragma unroll
    for (int mi = 0; mi < 4; mi++) {
#pragma unroll
        for (int nj = 0; nj < 4; nj++) {
            u32 k00 = enc16((u32)__bfloat16_as_ushort(__float2bfloat16(acc[mi][nj][0])));
            u32 k01 = enc16((u32)__bfloat16_as_ushort(__float2bfloat16(acc[mi][nj][1])));
            u32 k10 = enc16((u32)__bfloat16_as_ushort(__float2bfloat16(acc[mi][nj][2])));
            u32 k11 = enc16((u32)__bfloat16_as_ushort(__float2bfloat16(acc[mi][nj][3])));
            int r0 = wm0 + mi * 16 + tg;
            int cu = (wn0 + nj * 8) / 2 + tc;
            ep[r0 * 68 + cu] = (k01 << 16) | k00;
            ep[(r0 + 8) * 68 + cu] = (k11 << 16) | k10;
        }
    }
    __syncthreads();
#pragma unroll
    for (int it = 0; it < 8; it++) {
        int idx = tid + it * 256;
        int r = idx >> 4, c4 = idx & 15;
        uint4 v = *(uint4*)(ep + r * 68 + c4 * 4);
        *(uint4*)(g_samp + (size_t)(m_base + r) * NSAMP + n_base + c4 * 8) = v;
    }
}

// --- thresh: per-row exact sampled rank-SRANK key from g_samp
__global__ __launch_bounds__(256) void thresh_kernel() {
    __shared__ u16 keys[NSAMP];
    __shared__ u32 hist[256];
    __shared__ int s_b, s_rem;
    const int tid = threadIdx.x;
    const int row = blockIdx.x;

    for (int i = tid; i < 256; i += 256) hist[i] = 0;
    __syncthreads();
    for (int i = tid; i < NSAMP / 2; i += 256) {
        u32 v = ((const u32*)(g_samp + (size_t)row * NSAMP))[i];
        ((u32*)keys)[i] = v;
        atomicAdd(&hist[(v & 0xFFFFu) >> 8], 1u);
        atomicAdd(&hist[v >> 24], 1u);
    }
    __syncthreads();
    if (tid == 0) {
        int cum = 0, b = 255;
        for (; b > 0; b--) {
            int nb = cum + (int)hist[b];
            if (nb >= SRANK) break;
            cum = nb;
        }
        s_b = b;
        s_rem = SRANK - cum;
    }
    __syncthreads();
    const u32 bstar = (u32)s_b;
    for (int i = tid; i < 256; i += 256) hist[i] = 0;
    __syncthreads();
    for (int i = tid; i < NSAMP; i += 256) {
        u32 k = keys[i];
        if ((k >> 8) == bstar) atomicAdd(&hist[k & 255u], 1u);
    }
    __syncthreads();
    if (tid == 0) {
        int cum = 0, l = 255;
        for (; l > 0; l--) {
            cum += (int)hist[l];
            if (cum >= s_rem) break;
        }
        g_thr[row] = (bstar << 8) | (u32)l;
    }
}

// --- main GEMM: mbarrier producer/consumer pipeline, filtering epilogue
__global__ __launch_bounds__(256) void gemm_main() {
    extern __shared__ char dsm[];
    const u32 sb = smem_u32(dsm);
    const u32 mb = sb + NSTAGE * STAGE_B;   // full[s]=mb+8s, empty[s]=mb+24+8s
    const int tid = threadIdx.x;
    const int wid = tid >> 5, lane = tid & 31;
    const int m_base = blockIdx.x * GM;
    const int n_base = blockIdx.y * GN;
    const int warp_m = wid >> 2, warp_n = wid & 3;
    const int wm0 = warp_m * 64, wn0 = warp_n * 32;

    if (tid == 0) {
#pragma unroll
        for (int s = 0; s < NSTAGE; s++) {
            mbar_init(mb + 8 * s, 256);        // full[s]
            mbar_init(mb + 24 + 8 * s, 256);   // empty[s]
        }
    }
    __syncthreads();

    float acc[4][4][4];
#pragma unroll
    for (int i = 0; i < 4; i++)
#pragma unroll
        for (int j = 0; j < 4; j++)
#pragma unroll
            for (int q = 0; q < 4; q++) acc[i][j][q] = 0.0f;

    // preload stages 0,1
    issue_tile(sb, tid, m_base, n_base, 0);
    cpasync_arrive(mb + 0);
    issue_tile(sb + STAGE_B, tid, m_base, n_base, GK);
    cpasync_arrive(mb + 8);

    const int a_row_sel = lane & 15;
    const int a_kh = (lane >> 4) & 1;
    const int b_n_sel = (lane & 7) + ((lane & 16) >> 1);
    const int b_kh = (lane >> 3) & 1;

    for (int kt = 0; kt < NK; kt++) {
        const int s = kt % NSTAGE;
        waitp(mb + 8 * s, (u32)((kt / NSTAGE) & 1));
        const u32 abase = sb + s * STAGE_B;
        const u32 bbase = abase + GM * GK * 2;
        STAGE_MMAS(abase, bbase)
        mbar_arrive(mb + 24 + 8 * s);
        const int kt2 = kt + 2;
        if (kt2 < NK) {
            const int s2 = kt2 % NSTAGE;
            const int i2 = kt2 / NSTAGE;
            if (i2 >= 1)
                waitp(mb + 24 + 8 * s2, (u32)((i2 - 1) & 1));
            issue_tile(sb + s2 * STAGE_B, tid, m_base, n_base, kt2 * GK);
            cpasync_arrive(mb + 8 * s2);
        }
    }

    // filtering epilogue: registers -> (rare) global candidate appends
    const int tg = lane >> 2, tc = lane & 3;
#pragma unroll
    for (int mi = 0; mi < 4; mi++) {
        int r0 = m_base + wm0 + mi * 16 + tg;
        int r1 = r0 + 8;
        u32 tA = g_thr[r0], tB = g_thr[r1];
#pragma unroll
        for (int nj = 0; nj < 4; nj++) {
            int c0 = n_base + wn0 + nj * 8 + tc * 2;
#pragma unroll
            for (int q = 0; q < 4; q++) {
                int r = (q < 2) ? r0 : r1;
                u32 t = (q < 2) ? tA : tB;
                int c = c0 + (q & 1);
                u32 k = enc16((u32)__bfloat16_as_ushort(
                    __float2bfloat16(acc[mi][nj][q])));
                if (k >= t && c < N_TRAIN) {
                    u32 p = atomicAdd(&g_cnt2[r], 1u);
                    if (p < CCAP2)
                        g_cand2[(size_t)r * CCAP2 + p] = ((u64)k << 32) | (u32)c;
                }
            }
        }
    }
}

// -------- selB: refine + windowed exact rescore + sort + softmax + output
__global__ __launch_bounds__(256) void selB_kernel(
    const float* __restrict__ feats, const float* __restrict__ train,
    const int* __restrict__ labels, float* __restrict__ out) {
    __shared__ float4 fsh[256];
    __shared__ u64 buf[CCAP2];       // loose candidates, reused as sort buffer
    __shared__ u64 slist[NSURV];     // compacted survivors (key|idx)
    __shared__ u32 hist256[256];
    __shared__ float histc[NCLS];
    __shared__ float tw[MAXK];
    __shared__ int tl[MAXK];
    __shared__ float red[256];
    __shared__ u32 s_thr, s_ns, s_kmax;

    const int tid = threadIdx.x;
    const int wid = tid >> 5, lid = tid & 31;
    const int row = blockIdx.x;

    fsh[tid] = ((const float4*)(feats + (size_t)row * KDIM))[tid];
    for (int i = tid; i < 256; i += 256) hist256[i] = 0;
    if (tid == 0) { s_ns = 0; s_kmax = 0; }
    __syncthreads();

    const int C2 = min((int)g_cnt2[row], CCAP2);
    const u32 kthr = g_thr[row];
    u32 lmax = 0;
    for (int i = tid; i < C2; i += 256) {
        u64 e = g_cand2[(size_t)row * CCAP2 + i];
        buf[i] = e;
        u32 k = (u32)(e >> 32);
        if (k > lmax) lmax = k;
        atomicAdd(&hist256[min(255u, k - kthr)], 1u);
    }
    atomicMax(&s_kmax, lmax);
    __syncthreads();
    if (tid == 0) {
        int cum = 0, l = 255;
        for (; l > 0; l--) {
            cum += (int)hist256[l];
            if (cum >= MAXK) break;
        }
        u32 k200 = kthr + (u32)l;                // approx rank-200 key (lb)
        float vt = dec16(k200) - 1.5f;           // membership margin (proven)
        __nv_bfloat16 hb = __float2bfloat16_rd(vt);
        u32 t = enc16((u32)__bfloat16_as_ushort(hb));
        s_thr = t < kthr ? kthr : t;
    }
    __syncthreads();
    const u32 thr = s_thr;
    // exact-rescore window: keys >= key(max_val - RESC_WIN)
    u32 kwin;
    {
        float vw = dec16(s_kmax) - RESC_WIN;
        __nv_bfloat16 hb = __float2bfloat16_rd(vw);
        kwin = enc16((u32)__bfloat16_as_ushort(hb));
    }
    // compact survivors (~240)
    for (int i = tid; i < C2; i += 256) {
        u64 e = buf[i];
        if ((u32)(e >> 32) >= thr) {
            u32 p = atomicAdd(&s_ns, 1u);
            if (p < NSURV) slist[p] = e;
        }
    }
    __syncthreads();
    const int NS = min((int)s_ns, NSURV);

    // value assignment: exact fp32 dot ONLY within the window (~2-6/row);
    // others use the bf16 value (their softmax weight is < 1e-9 of the max).
    for (int base = 0; base < NS; base += 8) {
        int ci = base + wid;
        if (ci < NS) {
            u64 e = slist[ci];
            u32 k = (u32)(e >> 32);
            u32 idx = (u32)e;
            float val;
            if (k >= kwin) {
                const float4* tr = (const float4*)(train + (size_t)idx * KDIM);
                float s = 0.0f;
#pragma unroll
                for (int j = 0; j < 8; j++) {
                    float4 t = tr[j * 32 + lid];
                    float4 f = fsh[j * 32 + lid];
                    s += t.x * f.x + t.y * f.y + t.z * f.z + t.w * f.w;
                }
#pragma unroll
                for (int o = 16; o > 0; o >>= 1) s += __shfl_xor_sync(~0u, s, o);
                val = s;
            } else {
                val = dec16(k);
            }
            if (lid == 0)
                buf[ci] = ((u64)enc32(val) << 32) | (u32)(~idx);
        }
    }
    __syncthreads();
    int np2 = 256;
    while (np2 < NS) np2 <<= 1;
    for (int i = NS + tid; i < np2; i += 256) buf[i] = 0ULL;
    __syncthreads();
    // descending bitonic sort (value desc, idx asc on ties via ~idx)
    for (int k = 2; k <= np2; k <<= 1)
        for (int j = k >> 1; j > 0; j >>= 1) {
            for (int i = tid; i < np2; i += 256) {
                int ixj = i ^ j;
                if (ixj > i) {
                    u64 x = buf[i], y = buf[ixj];
                    bool desc = ((i & k) == 0);
                    if (desc ? (x < y) : (x > y)) { buf[i] = y; buf[ixj] = x; }
                }
            }
            __syncthreads();
        }
    // softmax over top-200 (exact values where weight matters)
    float smax = dec32((u32)(buf[0] >> 32));
    float w = 0.0f;
    int lab = 0;
    if (tid < MAXK && tid < NS) {
        u64 e = buf[tid];
        w = __expf((dec32((u32)(e >> 32)) - smax) * TINV);
        lab = labels[~(u32)e];
    }
    red[tid] = w;
    __syncthreads();
    for (int off = 128; off > 0; off >>= 1) {
        if (tid < off) red[tid] += red[tid + off];
        __syncthreads();
    }
    const float wsum = red[0];
    if (tid < MAXK) { tw[tid] = w / wsum; tl[tid] = lab; }
    for (int c = tid; c < NCLS; c += 256) histc[c] = 0.0f;
    __syncthreads();
    const int seg_lo[4] = {0, 10, 20, 100};
    const int seg_hi[4] = {10, 20, 100, 200};
    for (int ks = 0; ks < 4; ks++) {
        if (tid >= seg_lo[ks] && tid < seg_hi[ks])
            atomicAdd(&histc[tl[tid]], tw[tid]);
        __syncthreads();
        float* o = out + ((size_t)ks * B_ROWS + row) * NCLS;
        for (int c = tid; c < NCLS; c += 256) o[c] = histc[c];
        __syncthreads();
    }
}

// ---------------------------------------------------------------------------
extern "C" void kernel_launch(void* const* d_in, const int* in_sizes, int n_in,
                              void* d_out, int out_size) {
    const float* feats = (const float*)d_in[0];
    const float* train = (const float*)d_in[1];
    const int* labels = (const int*)d_in[2];
    float* out = (float*)d_out;

    static int inited = 0;
    if (!inited) {
        cudaFuncSetAttribute(gemm_mini,
                             cudaFuncAttributeMaxDynamicSharedMemorySize,
                             GEMM_SMEM);
        cudaFuncSetAttribute(gemm_main,
                             cudaFuncAttributeMaxDynamicSharedMemorySize,
                             GEMM_SMEM);
        inited = 1;
    }

    __nv_bfloat16* fb;
    __nv_bfloat16* tb;
    cudaGetSymbolAddress((void**)&fb, g_fb);
    cudaGetSymbolAddress((void**)&tb, g_tb);

    conv_kernel<<<256, 256>>>(feats, fb, B_ROWS * KDIM / 4);
    conv_kernel<<<2048, 256>>>(train, tb, N_TRAIN * KDIM / 4);
    zero_cnt<<<B_ROWS / 256, 256>>>();

    dim3 grid_mini(B_ROWS / GM, NSAMP / GN);
    gemm_mini<<<grid_mini, 256, GEMM_SMEM>>>();
    thresh_kernel<<<B_ROWS, 256>>>();

    dim3 grid_main(B_ROWS / GM, (N_TRAIN + GN - 1) / GN);
    gemm_main<<<grid_main, 256, GEMM_SMEM>>>();

    selB_kernel<<<B_ROWS, 256>>>(feats, train, labels, out);
}

// round 15
// speedup vs baseline: 1.4652x; 1.4652x over previous
#include <cuda_runtime.h>
#include <cuda_bf16.h>
#include <cstdint>

typedef unsigned long long u64;
typedef unsigned int u32;
typedef unsigned short u16;

#define B_ROWS 2048
#define N_TRAIN 100000
#define KDIM 1024
#define NCLS 1000
#define MAXK 200
#define NSAMP 2048         // sampled train rows for loose threshold
#define SRANK 24           // sampled rank -> true rank ~1170
#define CCAP2 3584         // loose-candidate cap per row (~7 sigma)
#define NSURV 1024         // survivor cap per row after refine
#define TINV (1.0f / 0.07f)
#define RESC_WIN 3.5f      // exact-rescore window below max (1.5 cut + 2*eps)

// device scratch (allocation-free)
__device__ __nv_bfloat16 g_fb[(size_t)B_ROWS * KDIM];     // 4 MB
__device__ __nv_bfloat16 g_tb[(size_t)N_TRAIN * KDIM];    // 205 MB
__device__ u16 g_samp[(size_t)B_ROWS * NSAMP];            // 8 MB (keys)
__device__ u32 g_thr[B_ROWS];                             // loose per-row key
__device__ u64 g_cand2[(size_t)B_ROWS * CCAP2];           // 59 MB (key|idx)
__device__ u32 g_cnt2[B_ROWS];

// ---------------------------------------------------------------- helpers
__device__ __forceinline__ u32 smem_u32(const void* p) {
    u32 a;
    asm("{ .reg .u64 t; cvta.to.shared.u64 t, %1; cvt.u32.u64 %0, t; }"
        : "=r"(a) : "l"(p));
    return a;
}
#define SWZ(x) ((x) ^ (((x) >> 3) & 0x70))

// 16-bit order keys over bf16 bit patterns
__device__ __forceinline__ u32 enc16(u32 x) {
    return (x & 0x8000u) ? ((~x) & 0xFFFFu) : (x | 0x8000u);
}
__device__ __forceinline__ float dec16(u32 k) {
    u32 b = (k & 0x8000u) ? (k & 0x7FFFu) : ((~k) & 0xFFFFu);
    return __uint_as_float(b << 16);
}
__device__ __forceinline__ u32 enc32(float f) {
    u32 u = __float_as_uint(f);
    return (u & 0x80000000u) ? ~u : (u | 0x80000000u);
}
__device__ __forceinline__ float dec32(u32 u) {
    return (u & 0x80000000u) ? __uint_as_float(u & 0x7FFFFFFFu)
                             : __uint_as_float(~u);
}

__device__ __forceinline__ void cp16(u32 dst, const void* src) {
    asm volatile("cp.async.cg.shared.global [%0], [%1], 16;"
                 :: "r"(dst), "l"(src) : "memory");
}
__device__ __forceinline__ void ldmx4(u32* r, u32 addr) {
    asm volatile("ldmatrix.sync.aligned.m8n8.x4.shared.b16 {%0,%1,%2,%3},[%4];"
                 : "=r"(r[0]), "=r"(r[1]), "=r"(r[2]), "=r"(r[3]) : "r"(addr));
}
__device__ __forceinline__ void mma16816(float* d, const u32* a, const u32* b) {
    asm volatile(
        "mma.sync.aligned.m16n8k16.row.col.f32.bf16.bf16.f32 "
        "{%0,%1,%2,%3},{%4,%5,%6,%7},{%8,%9},{%0,%1,%2,%3};"
        : "+f"(d[0]), "+f"(d[1]), "+f"(d[2]), "+f"(d[3])
        : "r"(a[0]), "r"(a[1]), "r"(a[2]), "r"(a[3]), "r"(b[0]), "r"(b[1]));
}
// mbarrier ops (sm_80/90-era PTX, legal on base compute_103)
__device__ __forceinline__ void mbar_init(u32 mbar, u32 cnt) {
    asm volatile("mbarrier.init.shared.b64 [%0], %1;" :: "r"(mbar), "r"(cnt)
                 : "memory");
}
__device__ __forceinline__ void mbar_arrive(u32 mbar) {
    asm volatile("mbarrier.arrive.shared.b64 _, [%0];" :: "r"(mbar) : "memory");
}
// .noinc is REQUIRED (non-noinc increments expected count -> deadlock, R10).
__device__ __forceinline__ void cpasync_arrive(u32 mbar) {
    asm volatile("cp.async.mbarrier.arrive.noinc.shared.b64 [%0];" :: "r"(mbar)
                 : "memory");
}
__device__ __forceinline__ void waitp(u32 mbar, u32 parity) {
    asm volatile(
        "{\n\t.reg .pred P;\n\t"
        "WL%=:\n\t"
        "mbarrier.try_wait.parity.acquire.cta.shared::cta.b64 P, [%0], %1, 0x989680;\n\t"
        "@P bra.uni WD%=;\n\t"
        "bra.uni WL%=;\n\t"
        "WD%=:\n\t}"
        :: "r"(mbar), "r"(parity) : "memory");
}

// ---------------------------------------------------------- fp32 -> bf16
__global__ __launch_bounds__(256) void conv_kernel(const float* __restrict__ src,
                                                   __nv_bfloat16* dst, int n4) {
    for (int i = blockIdx.x * 256 + threadIdx.x; i < n4; i += gridDim.x * 256) {
        float4 v = ((const float4*)src)[i];
        u32 lo, hi;
        asm("cvt.rn.bf16x2.f32 %0, %1, %2;" : "=r"(lo) : "f"(v.y), "f"(v.x));
        asm("cvt.rn.bf16x2.f32 %0, %1, %2;" : "=r"(hi) : "f"(v.w), "f"(v.z));
        ((uint2*)dst)[i] = make_uint2(lo, hi);
    }
}

__global__ void zero_cnt() { g_cnt2[blockIdx.x * 256 + threadIdx.x] = 0; }

// ------------------------------------------------- shared GEMM machinery
// CTA tile 128x128, BK=64, 8 warps (2x4), warp tile 64x32, 3-stage cp.async.
#define GM 128
#define GN 128
#define GK 64
#define STAGE_B (GM * GK * 2 + GN * GK * 2)   // 32768
#define NSTAGE 3
#define NK (KDIM / GK)                        // 16
#define GEMM_SMEM (NSTAGE * STAGE_B + 64)     // stages + 6 mbarriers

__device__ __forceinline__ void issue_tile(u32 sbase, int tid, int m_base,
                                           int n_base, int kt) {
#pragma unroll
    for (int q = 0; q < 4; q++) {
        int idx = tid + q * 256;
        int r = idx >> 3, c = idx & 7;
        const void* src = g_fb + ((size_t)(m_base + r) << 10) + kt + c * 8;
        cp16(sbase + SWZ(r * 128 + c * 16), src);
    }
    u32 bbase = sbase + GM * GK * 2;
#pragma unroll
    for (int q = 0; q < 4; q++) {
        int idx = tid + q * 256;
        int r = idx >> 3, c = idx & 7;
        int n = n_base + r;
        if (n >= N_TRAIN) n = N_TRAIN - 1;   // clamp: finite garbage, never emitted
        const void* src = g_tb + ((size_t)n << 10) + kt + c * 8;
        cp16(bbase + SWZ(r * 128 + c * 16), src);
    }
    asm volatile("cp.async.commit_group;" ::: "memory");
}

// MMA body for one resident stage (reads abase/bbase, updates acc)
#define STAGE_MMAS(abase_, bbase_)                                              \
    _Pragma("unroll")                                                           \
    for (int ks = 0; ks < 4; ks++) {                                            \
        u32 afrag[4][4], bfrag[2][4];                                           \
        _Pragma("unroll")                                                       \
        for (int mi = 0; mi < 4; mi++) {                                        \
            int row = wm0 + mi * 16 + a_row_sel;                                \
            int col = ks * 16 + a_kh * 8;                                       \
            ldmx4(afrag[mi], (abase_) + SWZ(row * 128 + col * 2));              \
        }                                                                       \
        _Pragma("unroll")                                                       \
        for (int p = 0; p < 2; p++) {                                           \
            int row = wn0 + p * 16 + b_n_sel;                                   \
            int col = ks * 16 + b_kh * 8;                                       \
            ldmx4(bfrag[p], (bbase_) + SWZ(row * 128 + col * 2));               \
        }                                                                       \
        _Pragma("unroll")                                                       \
        for (int mi = 0; mi < 4; mi++)                                          \
            _Pragma("unroll")                                                   \
            for (int nj = 0; nj < 4; nj++)                                      \
                mma16816(acc[mi][nj], afrag[mi],                                \
                         &bfrag[nj >> 1][(nj & 1) * 2]);                        \
    }

// barrier-lockstep mainloop (used by gemm_mini; proven config)
#define GEMM_MAINLOOP(acc)                                                      \
    issue_tile(sb, tid, m_base, n_base, 0);                                     \
    issue_tile(sb + STAGE_B, tid, m_base, n_base, GK);                          \
    const int a_row_sel = lane & 15;                                            \
    const int a_kh = (lane >> 4) & 1;                                           \
    const int b_n_sel = (lane & 7) + ((lane & 16) >> 1);                        \
    const int b_kh = (lane >> 3) & 1;                                           \
    for (int kt = 0; kt < NK; kt++) {                                           \
        asm volatile("cp.async.wait_group 1;" ::: "memory");                    \
        __syncthreads();                                                        \
        if (kt + 2 < NK)                                                        \
            issue_tile(sb + ((kt + 2) % NSTAGE) * STAGE_B, tid, m_base,         \
                       n_base, (kt + 2) * GK);                                  \
        const u32 abase = sb + (kt % NSTAGE) * STAGE_B;                         \
        const u32 bbase = abase + GM * GK * 2;                                  \
        STAGE_MMAS(abase, bbase)                                                \
    }                                                                           \
    asm volatile("cp.async.wait_group 0;" ::: "memory");                        \
    __syncthreads();

// --- mini GEMM: sampled columns (first NSAMP train rows) -> g_samp keys
__global__ __launch_bounds__(256) void gemm_mini() {
    extern __shared__ char dsm[];
    const u32 sb = smem_u32(dsm);
    const int tid = threadIdx.x;
    const int wid = tid >> 5, lane = tid & 31;
    const int m_base = blockIdx.x * GM;
    const int n_base = blockIdx.y * GN;
    const int warp_m = wid >> 2, warp_n = wid & 3;
    const int wm0 = warp_m * 64, wn0 = warp_n * 32;

    float acc[4][4][4];
#pragma unroll
    for (int i = 0; i < 4; i++)
#pragma unroll
        for (int j = 0; j < 4; j++)
#pragma unroll
            for (int q = 0; q < 4; q++) acc[i][j][q] = 0.0f;

    GEMM_MAINLOOP(acc)

    // epilogue: keys -> smem [128][68 u32] -> coalesced store to g_samp
    u32* ep = (u32*)dsm;
    const int tg = lane >> 2, tc = lane & 3;
#pragma unroll
    for (int mi = 0; mi < 4; mi++) {
#pragma unroll
        for (int nj = 0; nj < 4; nj++) {
            u32 k00 = enc16((u32)__bfloat16_as_ushort(__float2bfloat16(acc[mi][nj][0])));
            u32 k01 = enc16((u32)__bfloat16_as_ushort(__float2bfloat16(acc[mi][nj][1])));
            u32 k10 = enc16((u32)__bfloat16_as_ushort(__float2bfloat16(acc[mi][nj][2])));
            u32 k11 = enc16((u32)__bfloat16_as_ushort(__float2bfloat16(acc[mi][nj][3])));
            int r0 = wm0 + mi * 16 + tg;
            int cu = (wn0 + nj * 8) / 2 + tc;
            ep[r0 * 68 + cu] = (k01 << 16) | k00;
            ep[(r0 + 8) * 68 + cu] = (k11 << 16) | k10;
        }
    }
    __syncthreads();
#pragma unroll
    for (int it = 0; it < 8; it++) {
        int idx = tid + it * 256;
        int r = idx >> 4, c4 = idx & 15;
        uint4 v = *(uint4*)(ep + r * 68 + c4 * 4);
        *(uint4*)(g_samp + (size_t)(m_base + r) * NSAMP + n_base + c4 * 8) = v;
    }
}

// --- thresh: per-row exact sampled rank-SRANK key from g_samp
__global__ __launch_bounds__(256) void thresh_kernel() {
    __shared__ u16 keys[NSAMP];
    __shared__ u32 hist[256];
    __shared__ int s_b, s_rem;
    const int tid = threadIdx.x;
    const int row = blockIdx.x;

    for (int i = tid; i < 256; i += 256) hist[i] = 0;
    __syncthreads();
    for (int i = tid; i < NSAMP / 2; i += 256) {
        u32 v = ((const u32*)(g_samp + (size_t)row * NSAMP))[i];
        ((u32*)keys)[i] = v;
        atomicAdd(&hist[(v & 0xFFFFu) >> 8], 1u);
        atomicAdd(&hist[v >> 24], 1u);
    }
    __syncthreads();
    if (tid == 0) {
        int cum = 0, b = 255;
        for (; b > 0; b--) {
            int nb = cum + (int)hist[b];
            if (nb >= SRANK) break;
            cum = nb;
        }
        s_b = b;
        s_rem = SRANK - cum;
    }
    __syncthreads();
    const u32 bstar = (u32)s_b;
    for (int i = tid; i < 256; i += 256) hist[i] = 0;
    __syncthreads();
    for (int i = tid; i < NSAMP; i += 256) {
        u32 k = keys[i];
        if ((k >> 8) == bstar) atomicAdd(&hist[k & 255u], 1u);
    }
    __syncthreads();
    if (tid == 0) {
        int cum = 0, l = 255;
        for (; l > 0; l--) {
            cum += (int)hist[l];
            if (cum >= s_rem) break;
        }
        g_thr[row] = (bstar << 8) | (u32)l;
    }
}

// --- main GEMM: mbarrier producer/consumer pipeline, filtering epilogue
__global__ __launch_bounds__(256) void gemm_main() {
    extern __shared__ char dsm[];
    const u32 sb = smem_u32(dsm);
    const u32 mb = sb + NSTAGE * STAGE_B;   // full[s]=mb+8s, empty[s]=mb+24+8s
    const int tid = threadIdx.x;
    const int wid = tid >> 5, lane = tid & 31;
    const int m_base = blockIdx.x * GM;
    const int n_base = blockIdx.y * GN;
    const int warp_m = wid >> 2, warp_n = wid & 3;
    const int wm0 = warp_m * 64, wn0 = warp_n * 32;

    if (tid == 0) {
#pragma unroll
        for (int s = 0; s < NSTAGE; s++) {
            mbar_init(mb + 8 * s, 256);        // full[s]
            mbar_init(mb + 24 + 8 * s, 256);   // empty[s]
        }
    }
    __syncthreads();

    float acc[4][4][4];
#pragma unroll
    for (int i = 0; i < 4; i++)
#pragma unroll
        for (int j = 0; j < 4; j++)
#pragma unroll
            for (int q = 0; q < 4; q++) acc[i][j][q] = 0.0f;

    // preload stages 0,1
    issue_tile(sb, tid, m_base, n_base, 0);
    cpasync_arrive(mb + 0);
    issue_tile(sb + STAGE_B, tid, m_base, n_base, GK);
    cpasync_arrive(mb + 8);

    const int a_row_sel = lane & 15;
    const int a_kh = (lane >> 4) & 1;
    const int b_n_sel = (lane & 7) + ((lane & 16) >> 1);
    const int b_kh = (lane >> 3) & 1;

    for (int kt = 0; kt < NK; kt++) {
        const int s = kt % NSTAGE;
        waitp(mb + 8 * s, (u32)((kt / NSTAGE) & 1));
        const u32 abase = sb + s * STAGE_B;
        const u32 bbase = abase + GM * GK * 2;
        STAGE_MMAS(abase, bbase)
        mbar_arrive(mb + 24 + 8 * s);
        const int kt2 = kt + 2;
        if (kt2 < NK) {
            const int s2 = kt2 % NSTAGE;
            const int i2 = kt2 / NSTAGE;
            if (i2 >= 1)
                waitp(mb + 24 + 8 * s2, (u32)((i2 - 1) & 1));
            issue_tile(sb + s2 * STAGE_B, tid, m_base, n_base, kt2 * GK);
            cpasync_arrive(mb + 8 * s2);
        }
    }

    // filtering epilogue: registers -> (rare) global candidate appends
    const int tg = lane >> 2, tc = lane & 3;
#pragma unroll
    for (int mi = 0; mi < 4; mi++) {
        int r0 = m_base + wm0 + mi * 16 + tg;
        int r1 = r0 + 8;
        u32 tA = g_thr[r0], tB = g_thr[r1];
#pragma unroll
        for (int nj = 0; nj < 4; nj++) {
            int c0 = n_base + wn0 + nj * 8 + tc * 2;
#pragma unroll
            for (int q = 0; q < 4; q++) {
                int r = (q < 2) ? r0 : r1;
                u32 t = (q < 2) ? tA : tB;
                int c = c0 + (q & 1);
                u32 k = enc16((u32)__bfloat16_as_ushort(
                    __float2bfloat16(acc[mi][nj][q])));
                if (k >= t && c < N_TRAIN) {
                    u32 p = atomicAdd(&g_cnt2[r], 1u);
                    if (p < CCAP2)
                        g_cand2[(size_t)r * CCAP2 + p] = ((u64)k << 32) | (u32)c;
                }
            }
        }
    }
}

// -------- selB: refine + windowed exact rescore + sort + softmax + output
__global__ __launch_bounds__(256) void selB_kernel(
    const float* __restrict__ feats, const float* __restrict__ train,
    const int* __restrict__ labels, float* __restrict__ out) {
    __shared__ float4 fsh[256];
    __shared__ u64 buf[CCAP2];       // loose candidates, reused as sort buffer
    __shared__ u64 slist[NSURV];     // compacted survivors (key|idx)
    __shared__ u32 hist256[256];
    __shared__ float histc[NCLS];
    __shared__ float tw[MAXK];
    __shared__ int tl[MAXK];
    __shared__ float red[256];
    __shared__ u32 s_thr, s_ns, s_kmax;

    const int tid = threadIdx.x;
    const int wid = tid >> 5, lid = tid & 31;
    const int row = blockIdx.x;

    fsh[tid] = ((const float4*)(feats + (size_t)row * KDIM))[tid];
    for (int i = tid; i < 256; i += 256) hist256[i] = 0;
    if (tid == 0) { s_ns = 0; s_kmax = 0; }
    __syncthreads();

    const int C2 = min((int)g_cnt2[row], CCAP2);
    const u32 kthr = g_thr[row];
    u32 lmax = 0;
    for (int i = tid; i < C2; i += 256) {
        u64 e = g_cand2[(size_t)row * CCAP2 + i];
        buf[i] = e;
        u32 k = (u32)(e >> 32);
        if (k > lmax) lmax = k;
        atomicAdd(&hist256[min(255u, k - kthr)], 1u);
    }
    atomicMax(&s_kmax, lmax);
    __syncthreads();
    if (tid == 0) {
        int cum = 0, l = 255;
        for (; l > 0; l--) {
            cum += (int)hist256[l];
            if (cum >= MAXK) break;
        }
        u32 k200 = kthr + (u32)l;                // approx rank-200 key (lb)
        float vt = dec16(k200) - 1.5f;           // membership margin (proven)
        __nv_bfloat16 hb = __float2bfloat16_rd(vt);
        u32 t = enc16((u32)__bfloat16_as_ushort(hb));
        s_thr = t < kthr ? kthr : t;
    }
    __syncthreads();
    const u32 thr = s_thr;
    // exact-rescore window: keys >= key(max_val - RESC_WIN)
    u32 kwin;
    {
        float vw = dec16(s_kmax) - RESC_WIN;
        __nv_bfloat16 hb = __float2bfloat16_rd(vw);
        kwin = enc16((u32)__bfloat16_as_ushort(hb));
    }
    // compact survivors (~240)
    for (int i = tid; i < C2; i += 256) {
        u64 e = buf[i];
        if ((u32)(e >> 32) >= thr) {
            u32 p = atomicAdd(&s_ns, 1u);
            if (p < NSURV) slist[p] = e;
        }
    }
    __syncthreads();
    const int NS = min((int)s_ns, NSURV);

    // value assignment: exact fp32 dot ONLY within the window (~2-6/row);
    // others use the bf16 value (their softmax weight is < 1e-9 of the max).
    for (int base = 0; base < NS; base += 8) {
        int ci = base + wid;
        if (ci < NS) {
            u64 e = slist[ci];
            u32 k = (u32)(e >> 32);
            u32 idx = (u32)e;
            float val;
            if (k >= kwin) {
                const float4* tr = (const float4*)(train + (size_t)idx * KDIM);
                float s = 0.0f;
#pragma unroll
                for (int j = 0; j < 8; j++) {
                    float4 t = tr[j * 32 + lid];
                    float4 f = fsh[j * 32 + lid];
                    s += t.x * f.x + t.y * f.y + t.z * f.z + t.w * f.w;
                }
#pragma unroll
                for (int o = 16; o > 0; o >>= 1) s += __shfl_xor_sync(~0u, s, o);
                val = s;
            } else {
                val = dec16(k);
            }
            if (lid == 0)
                buf[ci] = ((u64)enc32(val) << 32) | (u32)(~idx);
        }
    }
    __syncthreads();
    int np2 = 256;
    while (np2 < NS) np2 <<= 1;
    for (int i = NS + tid; i < np2; i += 256) buf[i] = 0ULL;
    __syncthreads();
    // descending bitonic sort (value desc, idx asc on ties via ~idx)
    for (int k = 2; k <= np2; k <<= 1)
        for (int j = k >> 1; j > 0; j >>= 1) {
            for (int i = tid; i < np2; i += 256) {
                int ixj = i ^ j;
                if (ixj > i) {
                    u64 x = buf[i], y = buf[ixj];
                    bool desc = ((i & k) == 0);
                    if (desc ? (x < y) : (x > y)) { buf[i] = y; buf[ixj] = x; }
                }
            }
            __syncthreads();
        }
    // softmax over top-200 (exact values where weight matters)
    float smax = dec32((u32)(buf[0] >> 32));
    float w = 0.0f;
    int lab = 0;
    if (tid < MAXK && tid < NS) {
        u64 e = buf[tid];
        w = __expf((dec32((u32)(e >> 32)) - smax) * TINV);
        lab = labels[~(u32)e];
    }
    red[tid] = w;
    __syncthreads();
    for (int off = 128; off > 0; off >>= 1) {
        if (tid < off) red[tid] += red[tid + off];
        __syncthreads();
    }
    const float wsum = red[0];
    if (tid < MAXK) { tw[tid] = w / wsum; tl[tid] = lab; }
    for (int c = tid; c < NCLS; c += 256) histc[c] = 0.0f;
    __syncthreads();
    const int seg_lo[4] = {0, 10, 20, 100};
    const int seg_hi[4] = {10, 20, 100, 200};
    for (int ks = 0; ks < 4; ks++) {
        if (tid >= seg_lo[ks] && tid < seg_hi[ks])
            atomicAdd(&histc[tl[tid]], tw[tid]);
        __syncthreads();
        float* o = out + ((size_t)ks * B_ROWS + row) * NCLS;
        for (int c = tid; c < NCLS; c += 256) o[c] = histc[c];
        __syncthreads();
    }
}

// ---------------------------------------------------------------------------
extern "C" void kernel_launch(void* const* d_in, const int* in_sizes, int n_in,
                              void* d_out, int out_size) {
    const float* feats = (const float*)d_in[0];
    const float* train = (const float*)d_in[1];
    const int* labels = (const int*)d_in[2];
    float* out = (float*)d_out;

    static int inited = 0;
    if (!inited) {
        cudaFuncSetAttribute(gemm_mini,
                             cudaFuncAttributeMaxDynamicSharedMemorySize,
                             GEMM_SMEM);
        cudaFuncSetAttribute(gemm_main,
                             cudaFuncAttributeMaxDynamicSharedMemorySize,
                             GEMM_SMEM);
        inited = 1;
    }

    __nv_bfloat16* fb;
    __nv_bfloat16* tb;
    cudaGetSymbolAddress((void**)&fb, g_fb);
    cudaGetSymbolAddress((void**)&tb, g_tb);

    conv_kernel<<<256, 256>>>(feats, fb, B_ROWS * KDIM / 4);
    conv_kernel<<<2048, 256>>>(train, tb, N_TRAIN * KDIM / 4);
    zero_cnt<<<B_ROWS / 256, 256>>>();

    dim3 grid_mini(B_ROWS / GM, NSAMP / GN);
    gemm_mini<<<grid_mini, 256, GEMM_SMEM>>>();
    thresh_kernel<<<B_ROWS, 256>>>();

    dim3 grid_main(B_ROWS / GM, (N_TRAIN + GN - 1) / GN);
    gemm_main<<<grid_main, 256, GEMM_SMEM>>>();

    selB_kernel<<<B_ROWS, 256>>>(feats, train, labels, out);
}